// round 10
// baseline (speedup 1.0000x reference)
#include <cuda_runtime.h>
#include <math.h>
#include <stdint.h>

#define H 2048
#define E 64
#define TOPK 4
#define S 4096
#define SW 1024
#define NEGF (-3.4028234663852886e38f)   // float32 min
#define INV_SQRT_H 0.022097086912079608f // 1/sqrt(2048)

// scratch (device globals: allocation-free)
__device__ float g_wsT[H * E];    // K-major: g_wsT[h*E + e] = proj_w[e,h]*scale[h]*H^-0.5
__device__ int   g_gid[8 * S];    // vision group ids per (b, s)

typedef unsigned long long U64;

__device__ __forceinline__ void ffma2(U64 &d, U64 a, U64 b) {
    asm("fma.rn.f32x2 %0, %1, %2, %0;" : "+l"(d) : "l"(a), "l"(b));
}

// ---------------------------------------------------------------------------
// Kernel 1: fold scale & H^-0.5 into projection weights, TRANSPOSED to K-major
// ---------------------------------------------------------------------------
__global__ void ws_kernel(const float* __restrict__ proj_w,
                          const float* __restrict__ scale) {
    int i = blockIdx.x * blockDim.x + threadIdx.x;   // i = h*E + e
    if (i < E * H) {
        int h = i >> 6;
        int e = i & 63;
        g_wsT[i] = proj_w[e * H + h] * scale[h] * INV_SQRT_H;
    }
}

// ---------------------------------------------------------------------------
// Kernel 2: vision group ids (block-wide prefix scan, 1 block per batch row)
// ---------------------------------------------------------------------------
__global__ __launch_bounds__(1024) void gid_kernel(const int* __restrict__ mm) {
    int b = blockIdx.x;
    const int* row = mm + (size_t)b * S;
    int t = threadIdx.x;           // 1024 threads, 4 elems each
    int base = t * 4;

    int v[4];
    bool isv[4];
#pragma unroll
    for (int j = 0; j < 4; j++) {
        v[j] = row[base + j];
        isv[j] = (v[j] == 1) || (v[j] == 2);
    }
    bool prev = false;
    if (base > 0) {
        int p = row[base - 1];
        prev = (p == 1) || (p == 2);
    }
    int pre[4];
    int st[4];
    int cnt = 0;
#pragma unroll
    for (int j = 0; j < 4; j++) {
        st[j] = (isv[j] && !prev) ? 1 : 0;
        pre[j] = cnt;
        cnt += st[j];
        prev = isv[j];
    }

    __shared__ int sd[1024];
    sd[t] = cnt;
    __syncthreads();
    for (int off = 1; off < 1024; off <<= 1) {
        int val = sd[t];
        int add = (t >= off) ? sd[t - off] : 0;
        __syncthreads();
        sd[t] = val + add;
        __syncthreads();
    }
    int excl = sd[t] - cnt;
#pragma unroll
    for (int j = 0; j < 4; j++) {
        int incl = excl + pre[j] + st[j];
        g_gid[b * S + base + j] = isv[j] ? (incl - 1) : -1;
    }
}

// ---------------------------------------------------------------------------
// Kernel 3: build full + sliding additive masks
// ---------------------------------------------------------------------------
#define QT 4
__global__ __launch_bounds__(256) void mask_kernel(const int* __restrict__ packed,
                                                   float* __restrict__ fullm,
                                                   float* __restrict__ slidm) {
    __shared__ int sp[S];
    __shared__ int sg[S];

    const int nqb = S / QT;                    // 1024 blocks per batch
    int b = blockIdx.x / nqb;
    int qbase = (blockIdx.x % nqb) * QT;

    const int4* p4 = (const int4*)(packed + (size_t)b * S);
    const int4* g4 = (const int4*)(g_gid + (size_t)b * S);
    for (int i = threadIdx.x; i < S / 4; i += 256) {
        ((int4*)sp)[i] = p4[i];
        ((int4*)sg)[i] = g4[i];
    }
    __syncthreads();

#pragma unroll
    for (int qi = 0; qi < QT; qi++) {
        int q = qbase + qi;
        int pq = sp[q];
        int gq = sg[q];
        bool vq = (pq > 0);
        size_t rowoff = ((size_t)b * S + q) * (size_t)S;
        float4* fr = (float4*)(fullm + rowoff);
        float4* sr = (float4*)(slidm + rowoff);

        for (int i = threadIdx.x; i < S / 4; i += 256) {
            int kv = i * 4;
            float4 f, s;
            float* fp = (float*)&f;
            float* spv = (float*)&s;
#pragma unroll
            for (int j = 0; j < 4; j++) {
                int k = kv + j;
                int pk = sp[k];
                int gk = sg[k];
                bool same_doc = vq && (pq == pk);
                bool causal = (k <= q);
                bool fb = same_doc && causal;
                bool win = (q - k) < SW;
                bool svg = (gq >= 0) && (gq == gk);
                bool sb = (fb && win) || (svg && same_doc);
                fp[j]  = fb ? 0.0f : NEGF;
                spv[j] = sb ? 0.0f : NEGF;
            }
            fr[i] = f;
            sr[i] = s;
        }
    }
}

// ---------------------------------------------------------------------------
// Kernel 4: gate with fma.rn.f32x2.
//   64 threads/block, TM=32 tokens, tile 4 tok x 8 experts per thread.
//   x tile stored as DUPLICATED pairs (x,x) -> A operand is one LDS.64,
//   already splatted for f32x2 (no packing movs).
//   w tile K-major, thread reads experts {tx*4..+3} U {32+tx*4..+3}
//   (addr16 = 17k + tx / +8 -> conflict-free LDS.128 pairs).
// ---------------------------------------------------------------------------
#define TM 32
#define KC 16
#define SXD 36                 // x-dup tile row stride (floats) = 2*KC + 4
#define SWW 68                 // w tile row stride (floats)
#define NCH (H / KC)           // 128 chunks
#define XSTG (TM * SXD)        // 1152 floats per x stage
#define WSTG (KC * SWW)        // 1088 floats per w stage

__global__ __launch_bounds__(64) void gate_kernel(const float* __restrict__ x,
                                                  float* __restrict__ wout,
                                                  float* __restrict__ iout) {
    __shared__ float smx[2 * XSTG];     // dup x tiles (reused for logits)
    __shared__ float smw[2 * WSTG];     // w tiles (K-major)
    __shared__ float ssh[TM];           // per-token sum of squares

    const int t = threadIdx.x;
    const int n0 = blockIdx.x * TM;
    const int warp = t >> 5, lane = t & 31;
    const int tx = t & 7, ty = t >> 3;          // 8 x 8 thread grid

    // x loader: 2 float4 per chunk: rows r0 = t>>2 (0..15), r1 = r0+16
    const int r0 = t >> 2, c0 = (t & 3) * 4;    // c0 in {0,4,8,12}
    const int r1 = r0 + 16;
    const float* px0 = x + (size_t)(n0 + r0) * H + c0;
    const float* px1 = x + (size_t)(n0 + r1) * H + c0;
    const int sx0 = r0 * SXD + 2 * c0;          // dup-pair offsets
    const int sx1 = r1 * SXD + 2 * c0;

    // w loader: 4 float4 per chunk: rows (t>>4)+4q, col (t&15)*4
    const int wr = t >> 4;                      // 0..3
    const int wc = (t & 15) * 4;
    const float* pw = g_wsT + wr * E + wc;
    const int sw = wr * SWW + wc;

    if (t < TM) ssh[t] = 0.0f;

    float ssa = 0.0f, ssb = 0.0f;

    // prologue: chunk 0 -> stage 0
    {
        float4 lx0 = *(const float4*)px0;
        float4 lx1 = *(const float4*)px1;
        float4 a, b;
        a.x = lx0.x; a.y = lx0.x; a.z = lx0.y; a.w = lx0.y;
        b.x = lx0.z; b.y = lx0.z; b.z = lx0.w; b.w = lx0.w;
        *(float4*)(smx + sx0) = a;
        *(float4*)(smx + sx0 + 4) = b;
        a.x = lx1.x; a.y = lx1.x; a.z = lx1.y; a.w = lx1.y;
        b.x = lx1.z; b.y = lx1.z; b.z = lx1.w; b.w = lx1.w;
        *(float4*)(smx + sx1) = a;
        *(float4*)(smx + sx1 + 4) = b;
        ssa += lx0.x*lx0.x + lx0.y*lx0.y + lx0.z*lx0.z + lx0.w*lx0.w;
        ssb += lx1.x*lx1.x + lx1.y*lx1.y + lx1.z*lx1.z + lx1.w*lx1.w;
#pragma unroll
        for (int q = 0; q < 4; q++) {
            float4 w = *(const float4*)(pw + q * 4 * E);
            *(float4*)(smw + sw + q * 4 * SWW) = w;
        }
    }
    __syncthreads();

    U64 acc[4][4];          // [token i][expert-pair p]; p<2 -> e=tx*4+2p(+1), p>=2 -> 32+tx*4+2(p-2)(+1)
#pragma unroll
    for (int i = 0; i < 4; i++)
#pragma unroll
        for (int p = 0; p < 4; p++) acc[i][p] = 0ull;

    for (int c = 0; c < NCH; c++) {
        const int s = c & 1;
        float4 nx0, nx1, nw[4];
        const bool more = (c + 1 < NCH);
        if (more) {
            const int kox = (c + 1) * KC;
            nx0 = *(const float4*)(px0 + kox);
            nx1 = *(const float4*)(px1 + kox);
            const int kow = (c + 1) * KC * E;
#pragma unroll
            for (int q = 0; q < 4; q++)
                nw[q] = *(const float4*)(pw + kow + q * 4 * E);
        }

        const float* xb = smx + s * XSTG + (ty * 4) * SXD;
        const float* wb = smw + s * WSTG + tx * 4;
#pragma unroll
        for (int k = 0; k < KC; k++) {
            ulonglong2 b01 = *(const ulonglong2*)(wb + k * SWW);        // experts tx*4..+3
            ulonglong2 b23 = *(const ulonglong2*)(wb + k * SWW + 32);   // experts 32+tx*4..+3
            U64 a0 = *(const U64*)(xb + 0 * SXD + 2 * k);
            U64 a1 = *(const U64*)(xb + 1 * SXD + 2 * k);
            U64 a2 = *(const U64*)(xb + 2 * SXD + 2 * k);
            U64 a3 = *(const U64*)(xb + 3 * SXD + 2 * k);
            ffma2(acc[0][0], a0, b01.x); ffma2(acc[0][1], a0, b01.y);
            ffma2(acc[0][2], a0, b23.x); ffma2(acc[0][3], a0, b23.y);
            ffma2(acc[1][0], a1, b01.x); ffma2(acc[1][1], a1, b01.y);
            ffma2(acc[1][2], a1, b23.x); ffma2(acc[1][3], a1, b23.y);
            ffma2(acc[2][0], a2, b01.x); ffma2(acc[2][1], a2, b01.y);
            ffma2(acc[2][2], a2, b23.x); ffma2(acc[2][3], a2, b23.y);
            ffma2(acc[3][0], a3, b01.x); ffma2(acc[3][1], a3, b01.y);
            ffma2(acc[3][2], a3, b23.x); ffma2(acc[3][3], a3, b23.y);
        }

        if (more) {
            __syncthreads();
            const int dx = (s ^ 1) * XSTG;
            const int dw = (s ^ 1) * WSTG;
            float4 a, b;
            a.x = nx0.x; a.y = nx0.x; a.z = nx0.y; a.w = nx0.y;
            b.x = nx0.z; b.y = nx0.z; b.z = nx0.w; b.w = nx0.w;
            *(float4*)(smx + dx + sx0) = a;
            *(float4*)(smx + dx + sx0 + 4) = b;
            a.x = nx1.x; a.y = nx1.x; a.z = nx1.y; a.w = nx1.y;
            b.x = nx1.z; b.y = nx1.z; b.z = nx1.w; b.w = nx1.w;
            *(float4*)(smx + dx + sx1) = a;
            *(float4*)(smx + dx + sx1 + 4) = b;
            ssa += nx0.x*nx0.x + nx0.y*nx0.y + nx0.z*nx0.z + nx0.w*nx0.w;
            ssb += nx1.x*nx1.x + nx1.y*nx1.y + nx1.z*nx1.z + nx1.w*nx1.w;
#pragma unroll
            for (int q = 0; q < 4; q++)
                *(float4*)(smw + dw + sw + q * 4 * SWW) = nw[q];
            __syncthreads();
        }
    }

    atomicAdd(&ssh[r0], ssa);
    atomicAdd(&ssh[r1], ssb);
    __syncthreads();

    // logits -> reuse smx as [32][65]
    float* lsm = smx;
#pragma unroll
    for (int i = 0; i < 4; i++) {
        const int m = ty * 4 + i;
        const float iv = rsqrtf(ssh[m] * (1.0f / H) + 1e-6f);
#pragma unroll
        for (int p = 0; p < 4; p++) {
            float lo, hi;
            asm("mov.b64 {%0,%1}, %2;" : "=f"(lo), "=f"(hi) : "l"(acc[i][p]));
            const int e = (p < 2) ? (tx * 4 + 2 * p) : (32 + tx * 4 + 2 * (p - 2));
            lsm[m * 65 + e]     = lo * iv;
            lsm[m * 65 + e + 1] = hi * iv;
        }
    }
    __syncthreads();

    // ---- top-4 per token (2 warps x 16 tokens; 2 experts per lane) ----
#pragma unroll
    for (int i = 0; i < TM / 2; i++) {
        int tok = warp * 16 + i;
        float l0 = lsm[tok * 65 + lane];
        float l1 = lsm[tok * 65 + lane + 32];
        float m = fmaxf(l0, l1);
#pragma unroll
        for (int off = 16; off > 0; off >>= 1)
            m = fmaxf(m, __shfl_xor_sync(0xffffffffu, m, off));
        float e0 = __expf(l0 - m);
        float e1 = __expf(l1 - m);

        float wv[TOPK];
        int widx[TOPK];
        float wsum = 0.f;
#pragma unroll
        for (int r = 0; r < TOPK; r++) {
            float v; int idx;
            if (e0 >= e1) { v = e0; idx = lane; }
            else          { v = e1; idx = lane + 32; }
#pragma unroll
            for (int off = 16; off > 0; off >>= 1) {
                float ov = __shfl_xor_sync(0xffffffffu, v, off);
                int oi = __shfl_xor_sync(0xffffffffu, idx, off);
                if (ov > v || (ov == v && oi < idx)) { v = ov; idx = oi; }
            }
            wv[r] = v; widx[r] = idx; wsum += v;
            if (idx == lane)      e0 = -1.f;
            if (idx == lane + 32) e1 = -1.f;
        }
        if (lane == 0) {
            float inv = 1.f / fmaxf(wsum, 1e-20f);
            int o = (n0 + tok) * TOPK;
#pragma unroll
            for (int r = 0; r < TOPK; r++) {
                wout[o + r] = wv[r] * inv;
                iout[o + r] = (float)widx[r];
            }
        }
    }
}

// ---------------------------------------------------------------------------
extern "C" void kernel_launch(void* const* d_in, const int* in_sizes, int n_in,
                              void* d_out, int out_size) {
    const float* x      = (const float*)d_in[0];
    const int*   packed = (const int*)d_in[1];
    const int*   mm     = (const int*)d_in[2];
    const float* scale  = (const float*)d_in[3];
    const float* proj_w = (const float*)d_in[4];

    int Ntok = in_sizes[1];           // B*S
    int B = Ntok / S;

    float* out = (float*)d_out;
    size_t mask_elems = (size_t)B * S * S;
    float* fullm = out;
    float* slidm = out + mask_elems;
    float* wout  = out + 2 * mask_elems;
    float* iout  = wout + (size_t)Ntok * TOPK;

    ws_kernel<<<(E * H + 255) / 256, 256>>>(proj_w, scale);
    gid_kernel<<<B, 1024>>>(mm);
    mask_kernel<<<B * (S / QT), 256>>>(packed, fullm, slidm);
    gate_kernel<<<Ntok / TM, 64>>>(x, wout, iout);
}